// round 10
// baseline (speedup 1.0000x reference)
#include <cuda_runtime.h>
#include <cuda_fp16.h>
#include <cstdint>
#include <cstddef>

// ===========================================================================
// AttnBlock, fp16 mma.sync, token-major intermediates, 3-stage cp.async
// b=32, c=512, n=1024, groups=16
// ===========================================================================

#define BATCH 32
#define CCH   512
#define NTOK  1024
#define NGRP  16
#define CPG   (CCH / NGRP)
#define GSIZE (CPG * NTOK)

__device__ __half sc_hnT [(size_t)BATCH * NTOK * CCH];
__device__ __half sc_qkv [(size_t)BATCH * NTOK * 3 * CCH];
__device__ float  sc_s   [(size_t)BATCH * NTOK * NTOK];
__device__ __half sc_at  [(size_t)BATCH * NTOK * NTOK];
__device__ __half sc_oT  [(size_t)BATCH * NTOK * CCH];
__device__ __half sc_wcat[(size_t)3 * CCH * CCH];
__device__ __half sc_wp  [(size_t)CCH * CCH];
__device__ float  sc_bcat[3 * CCH];

// A / row-major-B tiles: [row 0..127][kw 0..31], pitch 36 words (18432 B).
// Trans-B tiles: [k 0..63][n 0..127 halves], pitch 68 words (17408 B).
// Both give 8-row word offsets {0,4,...,28} mod 32 -> ldmatrix conflict-free.
#define PITCHW  36
#define PITCHBT 68
#define STAGEB  36864                     // A (18432) + B (18432 slot)
#define NSTAGE  3
#define GEMM_SMEM_BYTES (NSTAGE * STAGEB) // 110592

__device__ __forceinline__ void cpa16(uint32_t saddr, const void* g) {
    asm volatile("cp.async.cg.shared.global [%0], [%1], 16;"
                 :: "r"(saddr), "l"(g));
}
#define CPA_COMMIT() asm volatile("cp.async.commit_group;" ::: "memory")
#define CPA_WAIT1()  asm volatile("cp.async.wait_group 1;" ::: "memory")
#define CPA_WAIT0()  asm volatile("cp.async.wait_group 0;" ::: "memory")

// row-major tile: 128 rows x 64 halves
__device__ __forceinline__ void cpa_tile(uint32_t sbase_bytes,
                                         const __half* __restrict__ src,
                                         int ld, int row0, int k0, int t) {
    #pragma unroll
    for (int j = 0; j < 4; j++) {
        const int idx = t + 256 * j;
        const int r = idx >> 3, c8 = idx & 7;
        const void* g = src + (size_t)(row0 + r) * ld + k0 + c8 * 8;
        cpa16(sbase_bytes + (uint32_t)(r * PITCHW + c8 * 4) * 4u, g);
    }
}

// trans tile: 64 k-rows x 128 n-halves (native [k][n] layout)
__device__ __forceinline__ void cpa_tile_bt(uint32_t sbase_bytes,
                                            const __half* __restrict__ src,
                                            int ld, int n0, int k0, int t) {
    #pragma unroll
    for (int j = 0; j < 4; j++) {
        const int idx = t + 256 * j;
        const int r = idx >> 4, c16 = idx & 15;
        const void* g = src + (size_t)(k0 + r) * ld + n0 + c16 * 8;
        cpa16(sbase_bytes + (uint32_t)(r * PITCHBT + c16 * 4) * 4u, g);
    }
}

__device__ __forceinline__ void mma16816(float d[4], const uint32_t a[4],
                                         const uint32_t b[2]) {
    asm volatile(
        "mma.sync.aligned.m16n8k16.row.col.f32.f16.f16.f32 "
        "{%0,%1,%2,%3}, {%4,%5,%6,%7}, {%8,%9}, {%0,%1,%2,%3};"
        : "+f"(d[0]), "+f"(d[1]), "+f"(d[2]), "+f"(d[3])
        : "r"(a[0]), "r"(a[1]), "r"(a[2]), "r"(a[3]), "r"(b[0]), "r"(b[1]));
}
#define LDMX4(r0, r1, r2, r3, addr) \
    asm volatile("ldmatrix.sync.aligned.m8n8.x4.shared.b16 {%0,%1,%2,%3}, [%4];" \
                 : "=r"(r0), "=r"(r1), "=r"(r2), "=r"(r3) : "r"(addr))
#define LDMX4T(r0, r1, r2, r3, addr) \
    asm volatile("ldmatrix.sync.aligned.m8n8.x4.trans.shared.b16 {%0,%1,%2,%3}, [%4];" \
                 : "=r"(r0), "=r"(r1), "=r"(r2), "=r"(r3) : "r"(addr))

// ---------------------------------------------------------------------------
// GEMM: C[m][n] = scale * sum_k A[m][k]*B'[n][k] (+bias) (+resid)
// A row-major. BT=0: B row-major [n][k]. BT=1: B native [k][n] + ldmatrix.trans.
// 128x128x64 tile, 8 warps, 3-stage cp.async, ONE syncthreads per chunk.
// ---------------------------------------------------------------------------
template<int BT, int BIASMODE, bool RESID, bool HOUT>
__global__ void __launch_bounds__(256, 2) hgemm(
    const __half* __restrict__ A, const __half* __restrict__ B,
    const float* __restrict__ bias, const float* __restrict__ resid,
    void* __restrict__ Cv, int N, int K, int ldA, int ldB,
    size_t sA, size_t sB, size_t sC, size_t sR, float scale)
{
    extern __shared__ __align__(16) uint32_t smbuf[];

    const int z = blockIdx.z;
    A += (size_t)z * sA;
    B += (size_t)z * sB;
    const float* R = RESID ? (resid + (size_t)z * sR) : nullptr;

    const int n0 = blockIdx.x * 128, m0 = blockIdx.y * 128;
    const int t = threadIdx.x;
    const int wid = t >> 5, lane = t & 31;
    const int wm = wid & 1, wn = wid >> 1;
    const int grp = lane >> 2, tig = lane & 3;

    const uint32_t smBase = (uint32_t)__cvta_generic_to_shared(smbuf);

    float acc[4][4][4] = {};

    // prologue: stages for chunks 0 and 1
    {
        cpa_tile(smBase, A, ldA, m0, 0, t);
        if (BT == 0) cpa_tile(smBase + 18432, B, ldB, n0, 0, t);
        else         cpa_tile_bt(smBase + 18432, B, ldB, n0, 0, t);
        CPA_COMMIT();
        cpa_tile(smBase + STAGEB, A, ldA, m0, 64, t);
        if (BT == 0) cpa_tile(smBase + STAGEB + 18432, B, ldB, n0, 64, t);
        else         cpa_tile_bt(smBase + STAGEB + 18432, B, ldB, n0, 64, t);
        CPA_COMMIT();
    }

    const uint32_t laneA =
        ((uint32_t)(wm * 64 + (lane & 7) + 8 * ((lane >> 3) & 1)) * PITCHW
         + 4u * ((lane >> 4) & 1)) * 4u;
    const uint32_t laneB0 =
        ((uint32_t)(wn * 32 + (lane & 7) + 8 * ((lane >> 4) & 1)) * PITCHW
         + 4u * ((lane >> 3) & 1)) * 4u;
    // trans-B: lanes 0-7 (klo,n0), 8-15 (khi,n0), 16-23 (klo,n0+8), 24-31 (khi,n0+8)
    const uint32_t laneBT =
        (uint32_t)((lane & 7) + 8 * ((lane >> 3) & 1)) * (PITCHBT * 4)
        + (uint32_t)(wn * 32 + 8 * ((lane >> 4) & 1)) * 2u;

    const int NK = K >> 6;
    for (int kc = 0; kc < NK; kc++) {
        if (kc + 1 < NK) CPA_WAIT1(); else CPA_WAIT0();
        __syncthreads();

        if (kc + 2 < NK) {
            const uint32_t nb = smBase + (uint32_t)(((kc + 2) % NSTAGE) * STAGEB);
            cpa_tile(nb, A, ldA, m0, (kc + 2) * 64, t);
            if (BT == 0) cpa_tile(nb + 18432, B, ldB, n0, (kc + 2) * 64, t);
            else         cpa_tile_bt(nb + 18432, B, ldB, n0, (kc + 2) * 64, t);
            CPA_COMMIT();
        }

        const uint32_t aBuf = smBase + (uint32_t)((kc % NSTAGE) * STAGEB);
        const uint32_t bBuf = aBuf + 18432u;
        #pragma unroll
        for (int ks = 0; ks < 4; ks++) {
            uint32_t af[4][4], bf[4][2];
            #pragma unroll
            for (int mf = 0; mf < 4; mf++)
                LDMX4(af[mf][0], af[mf][1], af[mf][2], af[mf][3],
                      aBuf + laneA + (uint32_t)(mf * 16 * PITCHW * 4 + ks * 32));
            if (BT == 0) {
                LDMX4(bf[0][0], bf[0][1], bf[1][0], bf[1][1],
                      bBuf + laneB0 + (uint32_t)(ks * 32));
                LDMX4(bf[2][0], bf[2][1], bf[3][0], bf[3][1],
                      bBuf + laneB0 + (uint32_t)(16 * PITCHW * 4 + ks * 32));
            } else {
                LDMX4T(bf[0][0], bf[0][1], bf[1][0], bf[1][1],
                       bBuf + laneBT + (uint32_t)(ks * 16 * PITCHBT * 4));
                LDMX4T(bf[2][0], bf[2][1], bf[3][0], bf[3][1],
                       bBuf + laneBT + (uint32_t)(ks * 16 * PITCHBT * 4 + 32));
            }
            #pragma unroll
            for (int mf = 0; mf < 4; mf++)
                #pragma unroll
                for (int nf = 0; nf < 4; nf++)
                    mma16816(acc[mf][nf], af[mf], bf[nf]);
        }
    }

    // ---- epilogue ----
    #pragma unroll
    for (int mf = 0; mf < 4; mf++) {
        const int r0 = m0 + wm * 64 + mf * 16 + grp;
        const float ba0 = (BIASMODE == 1) ? bias[r0] : 0.f;
        const float ba1 = (BIASMODE == 1) ? bias[r0 + 8] : 0.f;
        #pragma unroll
        for (int nf = 0; nf < 4; nf++) {
            const int cc = n0 + wn * 32 + nf * 8 + 2 * tig;
            float cb0 = 0.f, cb1 = 0.f;
            if (BIASMODE == 2) {
                const float2 cb = *reinterpret_cast<const float2*>(&bias[cc]);
                cb0 = cb.x; cb1 = cb.y;
            }
            float2 v0, v1;
            v0.x = acc[mf][nf][0] * scale + ba0 + cb0;
            v0.y = acc[mf][nf][1] * scale + ba0 + cb1;
            v1.x = acc[mf][nf][2] * scale + ba1 + cb0;
            v1.y = acc[mf][nf][3] * scale + ba1 + cb1;
            if (RESID) {
                const float2 q0 = *reinterpret_cast<const float2*>(&R[(size_t)r0 * N + cc]);
                const float2 q1 = *reinterpret_cast<const float2*>(&R[(size_t)(r0 + 8) * N + cc]);
                v0.x += q0.x; v0.y += q0.y;
                v1.x += q1.x; v1.y += q1.y;
            }
            if (HOUT) {
                __half* C = (__half*)Cv + (size_t)z * sC;
                *reinterpret_cast<__half2*>(&C[(size_t)r0 * N + cc]) =
                    __floats2half2_rn(v0.x, v0.y);
                *reinterpret_cast<__half2*>(&C[(size_t)(r0 + 8) * N + cc]) =
                    __floats2half2_rn(v1.x, v1.y);
            } else {
                float* C = (float*)Cv + (size_t)z * sC;
                *reinterpret_cast<float2*>(&C[(size_t)r0 * N + cc]) = v0;
                *reinterpret_cast<float2*>(&C[(size_t)(r0 + 8) * N + cc]) = v1;
            }
        }
    }
}

// ---------------------------------------------------------------------------
__global__ void __launch_bounds__(256) cvt_w_kernel(
    const float* __restrict__ w0, const float* __restrict__ w1,
    const float* __restrict__ w2, const float* __restrict__ w3,
    __half* __restrict__ wcat, __half* __restrict__ wp)
{
    const int zz = blockIdx.y;
    const float* src = (zz == 0) ? w0 : (zz == 1) ? w1 : (zz == 2) ? w2 : w3;
    __half* dst = (zz == 3) ? wp : (wcat + (size_t)zz * CCH * CCH);
    const int i = blockIdx.x * 256 + threadIdx.x;
    const float4 v = reinterpret_cast<const float4*>(src)[i];
    __half2* d = reinterpret_cast<__half2*>(dst) + i * 2;
    d[0] = __floats2half2_rn(v.x, v.y);
    d[1] = __floats2half2_rn(v.z, v.w);
}

__global__ void __launch_bounds__(256) bcat_kernel(
    const float* __restrict__ b0, const float* __restrict__ b1,
    const float* __restrict__ b2, float* __restrict__ bcat)
{
    const int i = blockIdx.x * 256 + threadIdx.x;
    bcat[i] = (i < 512) ? b0[i] : (i < 1024) ? b1[i - 512] : b2[i - 1024];
}

// ---------------------------------------------------------------------------
// GroupNorm -> token-major fp16
// ---------------------------------------------------------------------------
__global__ void __launch_bounds__(256) groupnorm_t_kernel(
    const float* __restrict__ x, const float* __restrict__ gamma,
    const float* __restrict__ beta, __half* __restrict__ hnT)
{
    const int g = blockIdx.x, b = blockIdx.y;
    const int c0 = g * CPG;
    const size_t xbase = ((size_t)b * CCH + c0) * NTOK;
    const int tid = threadIdx.x;

    const float4* xp = reinterpret_cast<const float4*>(x + xbase);
    float s = 0.f, ss = 0.f;
    for (int i = tid; i < GSIZE / 4; i += 256) {
        const float4 v = xp[i];
        s  += v.x + v.y + v.z + v.w;
        ss += v.x * v.x + v.y * v.y + v.z * v.z + v.w * v.w;
    }
    __shared__ float rs[256], rss[256];
    rs[tid] = s; rss[tid] = ss;
    __syncthreads();
    for (int w = 128; w > 0; w >>= 1) {
        if (tid < w) { rs[tid] += rs[tid + w]; rss[tid] += rss[tid + w]; }
        __syncthreads();
    }
    const float mean = rs[0] * (1.f / GSIZE);
    const float var  = rss[0] * (1.f / GSIZE) - mean * mean;
    const float rstd = rsqrtf(var + 1e-6f);

    __shared__ float gsc[CPG], gof[CPG];
    if (tid < CPG) {
        const float ga = gamma[c0 + tid] * rstd;
        gsc[tid] = ga;
        gof[tid] = beta[c0 + tid] - mean * ga;
    }
    __syncthreads();

    __shared__ __half smh[32 * 264];
    for (int tt = 0; tt < 4; tt++) {
        const int tok0 = tt * 256;
        #pragma unroll 4
        for (int j = 0; j < 32; j++) {
            const float val = x[xbase + (size_t)j * NTOK + tok0 + tid];
            smh[j * 264 + tid] = __float2half(val * gsc[j] + gof[j]);
        }
        __syncthreads();
        const size_t obase = ((size_t)b * NTOK + tok0 + tid) * CCH + c0;
        __half2 wb[16];
        #pragma unroll
        for (int j2 = 0; j2 < 16; j2++) {
            const __half lo = smh[(2 * j2) * 264 + tid];
            const __half hi = smh[(2 * j2 + 1) * 264 + tid];
            wb[j2] = __halves2half2(lo, hi);
        }
        #pragma unroll
        for (int qd = 0; qd < 4; qd++) {
            *reinterpret_cast<uint4*>(&hnT[obase + qd * 8]) =
                *reinterpret_cast<const uint4*>(&wb[qd * 4]);
        }
        __syncthreads();
    }
}

// ---------------------------------------------------------------------------
// Warp-per-row softmax: fp32 scores -> fp16 probs, pure shuffle reductions.
// ---------------------------------------------------------------------------
__global__ void __launch_bounds__(256) softmax_kernel(
    const float* __restrict__ s, __half* __restrict__ attn)
{
    const int wid = threadIdx.x >> 5, lane = threadIdx.x & 31;
    const size_t row = (size_t)blockIdx.y * NTOK + blockIdx.x * 8 + wid;
    const float4* p = reinterpret_cast<const float4*>(s + row * NTOK);
    __half2*      o = reinterpret_cast<__half2*>(attn + row * NTOK);

    float4 v[8];
    float m = -3.4e38f;
    #pragma unroll
    for (int i = 0; i < 8; i++) {
        v[i] = p[lane + 32 * i];
        m = fmaxf(m, fmaxf(fmaxf(v[i].x, v[i].y), fmaxf(v[i].z, v[i].w)));
    }
    #pragma unroll
    for (int off = 16; off > 0; off >>= 1)
        m = fmaxf(m, __shfl_xor_sync(0xFFFFFFFFu, m, off));

    float sum = 0.f;
    #pragma unroll
    for (int i = 0; i < 8; i++) {
        v[i].x = __expf(v[i].x - m); v[i].y = __expf(v[i].y - m);
        v[i].z = __expf(v[i].z - m); v[i].w = __expf(v[i].w - m);
        sum += v[i].x + v[i].y + v[i].z + v[i].w;
    }
    #pragma unroll
    for (int off = 16; off > 0; off >>= 1)
        sum += __shfl_xor_sync(0xFFFFFFFFu, sum, off);
    const float inv = 1.f / sum;

    #pragma unroll
    for (int i = 0; i < 8; i++) {
        o[(lane + 32 * i) * 2 + 0] = __floats2half2_rn(v[i].x * inv, v[i].y * inv);
        o[(lane + 32 * i) * 2 + 1] = __floats2half2_rn(v[i].z * inv, v[i].w * inv);
    }
}

// ---------------------------------------------------------------------------
extern "C" void kernel_launch(void* const* d_in, const int* in_sizes, int n_in,
                              void* d_out, int out_size)
{
    (void)in_sizes; (void)n_in; (void)out_size;
    const float* x     = (const float*)d_in[0];
    const float* gamma = (const float*)d_in[1];
    const float* beta  = (const float*)d_in[2];
    const float* wq    = (const float*)d_in[3];
    const float* bq    = (const float*)d_in[4];
    const float* wk    = (const float*)d_in[5];
    const float* bk    = (const float*)d_in[6];
    const float* wv    = (const float*)d_in[7];
    const float* bv    = (const float*)d_in[8];
    const float* wp    = (const float*)d_in[9];
    const float* bp    = (const float*)d_in[10];
    float* out = (float*)d_out;

    void *p0, *p1, *p2, *p3, *p4, *p5, *p6, *p7;
    cudaGetSymbolAddress(&p0, sc_hnT);
    cudaGetSymbolAddress(&p1, sc_qkv);
    cudaGetSymbolAddress(&p2, sc_s);
    cudaGetSymbolAddress(&p3, sc_at);
    cudaGetSymbolAddress(&p4, sc_oT);
    cudaGetSymbolAddress(&p5, sc_wcat);
    cudaGetSymbolAddress(&p6, sc_wp);
    cudaGetSymbolAddress(&p7, sc_bcat);
    __half* hnT  = (__half*)p0;
    __half* qkv  = (__half*)p1;
    float*  s    = (float*)p2;
    __half* at   = (__half*)p3;
    __half* oT   = (__half*)p4;
    __half* wcat = (__half*)p5;
    __half* whp  = (__half*)p6;
    float*  bcat = (float*)p7;

    const size_t sHN  = (size_t)NTOK * CCH;
    const size_t sQKV = (size_t)NTOK * 3 * CCH;
    const size_t sS   = (size_t)NTOK * NTOK;

    cudaFuncSetAttribute(hgemm<0, 2, false, true>,
        cudaFuncAttributeMaxDynamicSharedMemorySize, GEMM_SMEM_BYTES);
    cudaFuncSetAttribute(hgemm<0, 0, false, false>,
        cudaFuncAttributeMaxDynamicSharedMemorySize, GEMM_SMEM_BYTES);
    cudaFuncSetAttribute(hgemm<1, 0, false, true>,
        cudaFuncAttributeMaxDynamicSharedMemorySize, GEMM_SMEM_BYTES);
    cudaFuncSetAttribute(hgemm<0, 1, true, false>,
        cudaFuncAttributeMaxDynamicSharedMemorySize, GEMM_SMEM_BYTES);

    cvt_w_kernel<<<dim3(256, 4), 256>>>(wq, wk, wv, wp, wcat, whp);
    bcat_kernel<<<6, 256>>>(bq, bk, bv, bcat);
    groupnorm_t_kernel<<<dim3(NGRP, BATCH), 256>>>(x, gamma, beta, hnT);

    // 1) fused QKV
    hgemm<0, 2, false, true><<<dim3(12, 8, BATCH), 256, GEMM_SMEM_BYTES>>>(
        hnT, wcat, bcat, nullptr, qkv, 3 * CCH, CCH, CCH, CCH,
        sHN, 0, sQKV, 0, 1.f);

    // 2) scores
    hgemm<0, 0, false, false><<<dim3(8, 8, BATCH), 256, GEMM_SMEM_BYTES>>>(
        qkv, qkv + CCH, nullptr, nullptr, s, NTOK, CCH, 3 * CCH, 3 * CCH,
        sQKV, sQKV, sS, 0, 0.04419417382415922f);

    // 3) softmax
    softmax_kernel<<<dim3(NTOK / 8, BATCH), 256>>>(s, at);

    // 4) oT[n][c] = sum_m at[n][m] * v[m][c]  (B native [k][n], ldmatrix.trans)
    hgemm<1, 0, false, true><<<dim3(4, 8, BATCH), 256, GEMM_SMEM_BYTES>>>(
        at, qkv + 2 * CCH, nullptr, nullptr, oT, CCH, NTOK, NTOK, 3 * CCH,
        sS, sQKV, sHN, 0, 1.f);

    // 5) out = x + wp @ oT + bp
    hgemm<0, 1, true, false><<<dim3(8, 4, BATCH), 256, GEMM_SMEM_BYTES>>>(
        whp, oT, bp, x, out, NTOK, CCH, CCH, CCH,
        0, sHN, sHN, sHN, 1.f);
}

// round 11
// speedup vs baseline: 1.3838x; 1.3838x over previous
#include <cuda_runtime.h>
#include <cuda_fp16.h>
#include <cstdint>
#include <cstddef>

// ===========================================================================
// AttnBlock, fp16 mma.sync, token-major intermediates, cp.async pipeline,
// register double-buffered fragments. b=32, c=512, n=1024, groups=16
// ===========================================================================

#define BATCH 32
#define CCH   512
#define NTOK  1024
#define NGRP  16
#define CPG   (CCH / NGRP)
#define GSIZE (CPG * NTOK)

__device__ __half sc_hnT [(size_t)BATCH * NTOK * CCH];
__device__ __half sc_qkv [(size_t)BATCH * NTOK * 3 * CCH];
__device__ float  sc_s   [(size_t)BATCH * NTOK * NTOK];
__device__ __half sc_at  [(size_t)BATCH * NTOK * NTOK];
__device__ __half sc_oT  [(size_t)BATCH * NTOK * CCH];
__device__ __half sc_wcat[(size_t)3 * CCH * CCH];
__device__ __half sc_wp  [(size_t)CCH * CCH];
__device__ float  sc_bcat[3 * CCH];

// Smem operand: [row 0..127][kw 0..31] (kw = half-pair), pitch 36 words.
// ldmatrix conflict-free: 8 consecutive rows start at {0,4,...,28} mod 32.
#define PITCHW 36
#define OPW    (128 * PITCHW)              // 4608 words per operand buffer
#define GEMM_SMEM_BYTES (4 * OPW * 4)      // A0 B0 A1 B1 = 73728 B

__device__ __forceinline__ void cpa16(uint32_t saddr, const void* g) {
    asm volatile("cp.async.cg.shared.global [%0], [%1], 16;"
                 :: "r"(saddr), "l"(g));
}
#define CPA_COMMIT() asm volatile("cp.async.commit_group;" ::: "memory")
#define CPA_WAIT1()  asm volatile("cp.async.wait_group 1;" ::: "memory")
#define CPA_WAIT0()  asm volatile("cp.async.wait_group 0;" ::: "memory")

// TR0 tile via cp.async: 128 rows x 64 halves
__device__ __forceinline__ void cpa_tile(uint32_t sbase_bytes,
                                         const __half* __restrict__ src,
                                         int ld, int row0, int k0, int t) {
    #pragma unroll
    for (int j = 0; j < 4; j++) {
        const int idx = t + 256 * j;
        const int r = idx >> 3, c8 = idx & 7;
        const void* g = src + (size_t)(row0 + r) * ld + k0 + c8 * 8;
        cpa16(sbase_bytes + (uint32_t)(r * PITCHW + c8 * 4) * 4u, g);
    }
}

// TR1 (transpose) staging for 64-k chunk: src is [k][row].
struct StageT { uint32_t w[16]; };
__device__ __forceinline__ StageT ldgT(const __half* __restrict__ src,
                                       int ld, int row0, int k0, int t) {
    StageT st;
    const int kp = t & 31, nb = t >> 5;
    const __half* p = src + (size_t)(k0 + 2 * kp) * ld + row0 + nb * 16;
    const uint4 u0 = *reinterpret_cast<const uint4*>(p);
    const uint4 u1 = *reinterpret_cast<const uint4*>(p + ld);
    const uint4 u2 = *reinterpret_cast<const uint4*>(p + 8);
    const uint4 u3 = *reinterpret_cast<const uint4*>(p + ld + 8);
    st.w[0] = u0.x; st.w[1] = u0.y; st.w[2]  = u0.z; st.w[3]  = u0.w;
    st.w[4] = u1.x; st.w[5] = u1.y; st.w[6]  = u1.z; st.w[7]  = u1.w;
    st.w[8] = u2.x; st.w[9] = u2.y; st.w[10] = u2.z; st.w[11] = u2.w;
    st.w[12] = u3.x; st.w[13] = u3.y; st.w[14] = u3.z; st.w[15] = u3.w;
    return st;
}
__device__ __forceinline__ void stsT(uint32_t* __restrict__ buf,
                                     const StageT& st, int t) {
    const int kp = t & 31, nb = t >> 5;
    #pragma unroll
    for (int e2 = 0; e2 < 4; e2++) {
        const uint32_t lo0 = __byte_perm(st.w[e2],     st.w[4 + e2],  0x5410);
        const uint32_t hi0 = __byte_perm(st.w[e2],     st.w[4 + e2],  0x7632);
        const uint32_t lo1 = __byte_perm(st.w[8 + e2], st.w[12 + e2], 0x5410);
        const uint32_t hi1 = __byte_perm(st.w[8 + e2], st.w[12 + e2], 0x7632);
        buf[(nb * 16 + 2 * e2 + 0) * PITCHW + kp] = lo0;
        buf[(nb * 16 + 2 * e2 + 1) * PITCHW + kp] = hi0;
        buf[(nb * 16 + 8 + 2 * e2 + 0) * PITCHW + kp] = lo1;
        buf[(nb * 16 + 8 + 2 * e2 + 1) * PITCHW + kp] = hi1;
    }
}

__device__ __forceinline__ void mma16816(float d[4], const uint32_t a[4],
                                         const uint32_t b[2]) {
    asm volatile(
        "mma.sync.aligned.m16n8k16.row.col.f32.f16.f16.f32 "
        "{%0,%1,%2,%3}, {%4,%5,%6,%7}, {%8,%9}, {%0,%1,%2,%3};"
        : "+f"(d[0]), "+f"(d[1]), "+f"(d[2]), "+f"(d[3])
        : "r"(a[0]), "r"(a[1]), "r"(a[2]), "r"(a[3]), "r"(b[0]), "r"(b[1]));
}
#define LDMX4(r0, r1, r2, r3, addr) \
    asm volatile("ldmatrix.sync.aligned.m8n8.x4.shared.b16 {%0,%1,%2,%3}, [%4];" \
                 : "=r"(r0), "=r"(r1), "=r"(r2), "=r"(r3) : "r"(addr))

// Load one ks-step's fragments (A: 4x ldmatrix.x4, B: 2x ldmatrix.x4)
__device__ __forceinline__ void load_frags(uint32_t aBuf, uint32_t bBuf,
                                           uint32_t laneA, uint32_t laneB,
                                           int ks, uint32_t af[4][4],
                                           uint32_t bf[4][2]) {
    #pragma unroll
    for (int mf = 0; mf < 4; mf++)
        LDMX4(af[mf][0], af[mf][1], af[mf][2], af[mf][3],
              aBuf + laneA + (uint32_t)(mf * 16 * PITCHW * 4 + ks * 32));
    LDMX4(bf[0][0], bf[0][1], bf[1][0], bf[1][1],
          bBuf + laneB + (uint32_t)(ks * 32));
    LDMX4(bf[2][0], bf[2][1], bf[3][0], bf[3][1],
          bBuf + laneB + (uint32_t)(16 * PITCHW * 4 + ks * 32));
}

// ---------------------------------------------------------------------------
// GEMM: C[m][n] = scale * sum_k A[m][k]*B'[n][k] (+bias) (+resid)
// A row-major (cp.async). BT=0: B row-major [n][k] (cp.async);
// BT=1: B stored [k][n] (register transpose). BIASMODE 0/1(row)/2(col).
// 128x128x64 tile, 8 warps, 2-stage double buffer, reg-double-buffered frags.
// ---------------------------------------------------------------------------
template<int BT, int BIASMODE, bool RESID, bool HOUT>
__global__ void __launch_bounds__(256) hgemm(
    const __half* __restrict__ A, const __half* __restrict__ B,
    const float* __restrict__ bias, const float* __restrict__ resid,
    void* __restrict__ Cv, int N, int K, int ldA, int ldB,
    size_t sA, size_t sB, size_t sC, size_t sR, float scale)
{
    extern __shared__ __align__(16) uint32_t smbuf[];

    const int z = blockIdx.z;
    A += (size_t)z * sA;
    B += (size_t)z * sB;
    const float* R = RESID ? (resid + (size_t)z * sR) : nullptr;

    const int n0 = blockIdx.x * 128, m0 = blockIdx.y * 128;
    const int t = threadIdx.x;
    const int wid = t >> 5, lane = t & 31;
    const int wm = wid & 1, wn = wid >> 1;
    const int grp = lane >> 2, tig = lane & 3;

    const uint32_t smBase = (uint32_t)__cvta_generic_to_shared(smbuf);
    // buffers (byte offsets): A0=0, B0=OPW*4, A1=2*OPW*4, B1=3*OPW*4

    float acc[4][4][4] = {};
    StageT stB;

    // prologue: chunk 0
    cpa_tile(smBase, A, ldA, m0, 0, t);
    if (BT == 0) cpa_tile(smBase + OPW * 4, B, ldB, n0, 0, t);
    CPA_COMMIT();
    if (BT == 1) {
        stB = ldgT(B, ldB, n0, 0, t);
        stsT(smbuf + OPW, stB, t);
    }

    const uint32_t laneA =
        ((uint32_t)(wm * 64 + (lane & 7) + 8 * ((lane >> 3) & 1)) * PITCHW
         + 4u * ((lane >> 4) & 1)) * 4u;
    const uint32_t laneB =
        ((uint32_t)(wn * 32 + (lane & 7) + 8 * ((lane >> 4) & 1)) * PITCHW
         + 4u * ((lane >> 3) & 1)) * 4u;

    const int NK = K >> 6;
    for (int kc = 0; kc < NK; kc++) {
        const bool more = (kc + 1 < NK);
        const uint32_t cur = (kc & 1) ? (uint32_t)(2 * OPW * 4) : 0u;
        const uint32_t nxt = (kc & 1) ? 0u : (uint32_t)(2 * OPW * 4);
        if (more) {
            cpa_tile(smBase + nxt, A, ldA, m0, (kc + 1) * 64, t);
            if (BT == 0) cpa_tile(smBase + nxt + OPW * 4, B, ldB, n0, (kc + 1) * 64, t);
            CPA_COMMIT();
            if (BT == 1) stB = ldgT(B, ldB, n0, (kc + 1) * 64, t);
        }
        if (more) CPA_WAIT1(); else CPA_WAIT0();
        __syncthreads();

        const uint32_t aBuf = smBase + cur;
        const uint32_t bBuf = aBuf + (uint32_t)(OPW * 4);

        // register double-buffered fragments across ks
        uint32_t af[2][4][4], bf[2][4][2];
        load_frags(aBuf, bBuf, laneA, laneB, 0, af[0], bf[0]);
        #pragma unroll
        for (int ks = 0; ks < 4; ks++) {
            const int cb = ks & 1;
            if (ks < 3)
                load_frags(aBuf, bBuf, laneA, laneB, ks + 1, af[cb ^ 1], bf[cb ^ 1]);
            #pragma unroll
            for (int mf = 0; mf < 4; mf++)
                #pragma unroll
                for (int nf = 0; nf < 4; nf++)
                    mma16816(acc[mf][nf], af[cb][mf], bf[cb][nf]);
        }

        if (BT == 1 && more) {
            uint32_t* nB = smbuf + (nxt >> 2) + OPW;
            stsT(nB, stB, t);
        }
        __syncthreads();
    }

    // ---- epilogue ----
    #pragma unroll
    for (int mf = 0; mf < 4; mf++) {
        const int r0 = m0 + wm * 64 + mf * 16 + grp;
        const float ba0 = (BIASMODE == 1) ? bias[r0] : 0.f;
        const float ba1 = (BIASMODE == 1) ? bias[r0 + 8] : 0.f;
        #pragma unroll
        for (int nf = 0; nf < 4; nf++) {
            const int cc = n0 + wn * 32 + nf * 8 + 2 * tig;
            float cb0 = 0.f, cb1 = 0.f;
            if (BIASMODE == 2) {
                const float2 cb = *reinterpret_cast<const float2*>(&bias[cc]);
                cb0 = cb.x; cb1 = cb.y;
            }
            float2 v0, v1;
            v0.x = acc[mf][nf][0] * scale + ba0 + cb0;
            v0.y = acc[mf][nf][1] * scale + ba0 + cb1;
            v1.x = acc[mf][nf][2] * scale + ba1 + cb0;
            v1.y = acc[mf][nf][3] * scale + ba1 + cb1;
            if (RESID) {
                const float2 q0 = *reinterpret_cast<const float2*>(&R[(size_t)r0 * N + cc]);
                const float2 q1 = *reinterpret_cast<const float2*>(&R[(size_t)(r0 + 8) * N + cc]);
                v0.x += q0.x; v0.y += q0.y;
                v1.x += q1.x; v1.y += q1.y;
            }
            if (HOUT) {
                __half* C = (__half*)Cv + (size_t)z * sC;
                *reinterpret_cast<__half2*>(&C[(size_t)r0 * N + cc]) =
                    __floats2half2_rn(v0.x, v0.y);
                *reinterpret_cast<__half2*>(&C[(size_t)(r0 + 8) * N + cc]) =
                    __floats2half2_rn(v1.x, v1.y);
            } else {
                float* C = (float*)Cv + (size_t)z * sC;
                *reinterpret_cast<float2*>(&C[(size_t)r0 * N + cc]) = v0;
                *reinterpret_cast<float2*>(&C[(size_t)(r0 + 8) * N + cc]) = v1;
            }
        }
    }
}

// ---------------------------------------------------------------------------
__global__ void __launch_bounds__(256) cvt_w_kernel(
    const float* __restrict__ w0, const float* __restrict__ w1,
    const float* __restrict__ w2, const float* __restrict__ w3,
    __half* __restrict__ wcat, __half* __restrict__ wp)
{
    const int zz = blockIdx.y;
    const float* src = (zz == 0) ? w0 : (zz == 1) ? w1 : (zz == 2) ? w2 : w3;
    __half* dst = (zz == 3) ? wp : (wcat + (size_t)zz * CCH * CCH);
    const int i = blockIdx.x * 256 + threadIdx.x;
    const float4 v = reinterpret_cast<const float4*>(src)[i];
    __half2* d = reinterpret_cast<__half2*>(dst) + i * 2;
    d[0] = __floats2half2_rn(v.x, v.y);
    d[1] = __floats2half2_rn(v.z, v.w);
}

__global__ void __launch_bounds__(256) bcat_kernel(
    const float* __restrict__ b0, const float* __restrict__ b1,
    const float* __restrict__ b2, float* __restrict__ bcat)
{
    const int i = blockIdx.x * 256 + threadIdx.x;
    bcat[i] = (i < 512) ? b0[i] : (i < 1024) ? b1[i - 512] : b2[i - 1024];
}

// ---------------------------------------------------------------------------
// GroupNorm -> token-major fp16
// ---------------------------------------------------------------------------
__global__ void __launch_bounds__(256) groupnorm_t_kernel(
    const float* __restrict__ x, const float* __restrict__ gamma,
    const float* __restrict__ beta, __half* __restrict__ hnT)
{
    const int g = blockIdx.x, b = blockIdx.y;
    const int c0 = g * CPG;
    const size_t xbase = ((size_t)b * CCH + c0) * NTOK;
    const int tid = threadIdx.x;

    const float4* xp = reinterpret_cast<const float4*>(x + xbase);
    float s = 0.f, ss = 0.f;
    for (int i = tid; i < GSIZE / 4; i += 256) {
        const float4 v = xp[i];
        s  += v.x + v.y + v.z + v.w;
        ss += v.x * v.x + v.y * v.y + v.z * v.z + v.w * v.w;
    }
    __shared__ float rs[256], rss[256];
    rs[tid] = s; rss[tid] = ss;
    __syncthreads();
    for (int w = 128; w > 0; w >>= 1) {
        if (tid < w) { rs[tid] += rs[tid + w]; rss[tid] += rss[tid + w]; }
        __syncthreads();
    }
    const float mean = rs[0] * (1.f / GSIZE);
    const float var  = rss[0] * (1.f / GSIZE) - mean * mean;
    const float rstd = rsqrtf(var + 1e-6f);

    __shared__ float gsc[CPG], gof[CPG];
    if (tid < CPG) {
        const float ga = gamma[c0 + tid] * rstd;
        gsc[tid] = ga;
        gof[tid] = beta[c0 + tid] - mean * ga;
    }
    __syncthreads();

    __shared__ __half smh[32 * 264];
    for (int tt = 0; tt < 4; tt++) {
        const int tok0 = tt * 256;
        #pragma unroll 4
        for (int j = 0; j < 32; j++) {
            const float val = x[xbase + (size_t)j * NTOK + tok0 + tid];
            smh[j * 264 + tid] = __float2half(val * gsc[j] + gof[j]);
        }
        __syncthreads();
        const size_t obase = ((size_t)b * NTOK + tok0 + tid) * CCH + c0;
        __half2 wb[16];
        #pragma unroll
        for (int j2 = 0; j2 < 16; j2++) {
            const __half lo = smh[(2 * j2) * 264 + tid];
            const __half hi = smh[(2 * j2 + 1) * 264 + tid];
            wb[j2] = __halves2half2(lo, hi);
        }
        #pragma unroll
        for (int qd = 0; qd < 4; qd++) {
            *reinterpret_cast<uint4*>(&hnT[obase + qd * 8]) =
                *reinterpret_cast<const uint4*>(&wb[qd * 4]);
        }
        __syncthreads();
    }
}

// ---------------------------------------------------------------------------
// Warp-per-row softmax: fp32 scores -> fp16 probs, pure shuffle reductions.
// (per-row max == reference's global shift, by softmax shift invariance)
// ---------------------------------------------------------------------------
__global__ void __launch_bounds__(256) softmax_kernel(
    const float* __restrict__ s, __half* __restrict__ attn)
{
    const int wid = threadIdx.x >> 5, lane = threadIdx.x & 31;
    const size_t row = (size_t)blockIdx.y * NTOK + blockIdx.x * 8 + wid;
    const float4* p = reinterpret_cast<const float4*>(s + row * NTOK);
    __half2*      o = reinterpret_cast<__half2*>(attn + row * NTOK);

    float4 v[8];
    float m = -3.4e38f;
    #pragma unroll
    for (int i = 0; i < 8; i++) {
        v[i] = p[lane + 32 * i];
        m = fmaxf(m, fmaxf(fmaxf(v[i].x, v[i].y), fmaxf(v[i].z, v[i].w)));
    }
    #pragma unroll
    for (int off = 16; off > 0; off >>= 1)
        m = fmaxf(m, __shfl_xor_sync(0xFFFFFFFFu, m, off));

    float sum = 0.f;
    #pragma unroll
    for (int i = 0; i < 8; i++) {
        v[i].x = __expf(v[i].x - m); v[i].y = __expf(v[i].y - m);
        v[i].z = __expf(v[i].z - m); v[i].w = __expf(v[i].w - m);
        sum += v[i].x + v[i].y + v[i].z + v[i].w;
    }
    #pragma unroll
    for (int off = 16; off > 0; off >>= 1)
        sum += __shfl_xor_sync(0xFFFFFFFFu, sum, off);
    const float inv = 1.f / sum;

    #pragma unroll
    for (int i = 0; i < 8; i++) {
        o[(lane + 32 * i) * 2 + 0] = __floats2half2_rn(v[i].x * inv, v[i].y * inv);
        o[(lane + 32 * i) * 2 + 1] = __floats2half2_rn(v[i].z * inv, v[i].w * inv);
    }
}

// ---------------------------------------------------------------------------
extern "C" void kernel_launch(void* const* d_in, const int* in_sizes, int n_in,
                              void* d_out, int out_size)
{
    (void)in_sizes; (void)n_in; (void)out_size;
    const float* x     = (const float*)d_in[0];
    const float* gamma = (const float*)d_in[1];
    const float* beta  = (const float*)d_in[2];
    const float* wq    = (const float*)d_in[3];
    const float* bq    = (const float*)d_in[4];
    const float* wk    = (const float*)d_in[5];
    const float* bk    = (const float*)d_in[6];
    const float* wv    = (const float*)d_in[7];
    const float* bv    = (const float*)d_in[8];
    const float* wp    = (const float*)d_in[9];
    const float* bp    = (const float*)d_in[10];
    float* out = (float*)d_out;

    void *p0, *p1, *p2, *p3, *p4, *p5, *p6, *p7;
    cudaGetSymbolAddress(&p0, sc_hnT);
    cudaGetSymbolAddress(&p1, sc_qkv);
    cudaGetSymbolAddress(&p2, sc_s);
    cudaGetSymbolAddress(&p3, sc_at);
    cudaGetSymbolAddress(&p4, sc_oT);
    cudaGetSymbolAddress(&p5, sc_wcat);
    cudaGetSymbolAddress(&p6, sc_wp);
    cudaGetSymbolAddress(&p7, sc_bcat);
    __half* hnT  = (__half*)p0;
    __half* qkv  = (__half*)p1;
    float*  s    = (float*)p2;
    __half* at   = (__half*)p3;
    __half* oT   = (__half*)p4;
    __half* wcat = (__half*)p5;
    __half* whp  = (__half*)p6;
    float*  bcat = (float*)p7;

    const size_t sHN  = (size_t)NTOK * CCH;
    const size_t sQKV = (size_t)NTOK * 3 * CCH;
    const size_t sS   = (size_t)NTOK * NTOK;

    cudaFuncSetAttribute(hgemm<0, 2, false, true>,
        cudaFuncAttributeMaxDynamicSharedMemorySize, GEMM_SMEM_BYTES);
    cudaFuncSetAttribute(hgemm<0, 0, false, false>,
        cudaFuncAttributeMaxDynamicSharedMemorySize, GEMM_SMEM_BYTES);
    cudaFuncSetAttribute(hgemm<1, 0, false, true>,
        cudaFuncAttributeMaxDynamicSharedMemorySize, GEMM_SMEM_BYTES);
    cudaFuncSetAttribute(hgemm<0, 1, true, false>,
        cudaFuncAttributeMaxDynamicSharedMemorySize, GEMM_SMEM_BYTES);

    cvt_w_kernel<<<dim3(256, 4), 256>>>(wq, wk, wv, wp, wcat, whp);
    bcat_kernel<<<6, 256>>>(bq, bk, bv, bcat);
    groupnorm_t_kernel<<<dim3(NGRP, BATCH), 256>>>(x, gamma, beta, hnT);

    // 1) fused QKV: qkv[token][oc'] = hnT[token][c] . wcat[oc'][c] + bcat[oc']
    hgemm<0, 2, false, true><<<dim3(12, 8, BATCH), 256, GEMM_SMEM_BYTES>>>(
        hnT, wcat, bcat, nullptr, qkv, 3 * CCH, CCH, CCH, CCH,
        sHN, 0, sQKV, 0, 1.f);

    // 2) scores s[n][m] = scale * q[n][:] . k[m][:]
    hgemm<0, 0, false, false><<<dim3(8, 8, BATCH), 256, GEMM_SMEM_BYTES>>>(
        qkv, qkv + CCH, nullptr, nullptr, s, NTOK, CCH, 3 * CCH, 3 * CCH,
        sQKV, sQKV, sS, 0, 0.04419417382415922f);

    // 3) softmax
    softmax_kernel<<<dim3(NTOK / 8, BATCH), 256>>>(s, at);

    // 4) oT[n][c] = sum_m at[n][m] * v[m][c]   (B stored [m][c] -> TR1)
    hgemm<1, 0, false, true><<<dim3(4, 8, BATCH), 256, GEMM_SMEM_BYTES>>>(
        at, qkv + 2 * CCH, nullptr, nullptr, oT, CCH, NTOK, NTOK, 3 * CCH,
        sS, sQKV, sHN, 0, 1.f);

    // 5) out[oc][n] = x + wp[oc][:] . oT[n][:] + bp[oc]
    hgemm<0, 1, true, false><<<dim3(8, 4, BATCH), 256, GEMM_SMEM_BYTES>>>(
        whp, oT, bp, x, out, NTOK, CCH, CCH, CCH,
        0, sHN, sHN, sHN, 1.f);
}

// round 12
// speedup vs baseline: 1.5120x; 1.0927x over previous
#include <cuda_runtime.h>
#include <cuda_fp16.h>
#include <cstdint>
#include <cstddef>

// ===========================================================================
// AttnBlock, fp16 mma.sync, token-major intermediates, cp.async pipeline,
// register double-buffered fragments; trans-B via cp.async + ldmatrix.trans.
// b=32, c=512, n=1024, groups=16
// ===========================================================================

#define BATCH 32
#define CCH   512
#define NTOK  1024
#define NGRP  16
#define CPG   (CCH / NGRP)
#define GSIZE (CPG * NTOK)

__device__ __half sc_hnT [(size_t)BATCH * NTOK * CCH];
__device__ __half sc_qkv [(size_t)BATCH * NTOK * 3 * CCH];
__device__ float  sc_s   [(size_t)BATCH * NTOK * NTOK];
__device__ __half sc_at  [(size_t)BATCH * NTOK * NTOK];
__device__ __half sc_oT  [(size_t)BATCH * NTOK * CCH];
__device__ __half sc_wcat[(size_t)3 * CCH * CCH];
__device__ __half sc_wp  [(size_t)CCH * CCH];
__device__ float  sc_bcat[3 * CCH];

// Row-major operand: [row 0..127][kw 0..31], pitch 36 words (18432 B).
// Trans-B operand:   [k 0..63][n-half 0..63], pitch 68 words (17408 B).
// Both: 8 consecutive rows start at {0,4,...,28} mod 32 -> ldmatrix
// 16B-granule reads tile all 32 banks, conflict-free.
#define PITCHW  36
#define PITCHBT 68
#define OPW     (128 * PITCHW)             // words per operand slot (4608)
#define GEMM_SMEM_BYTES (4 * OPW * 4)      // A0 B0 A1 B1 = 73728 B

__device__ __forceinline__ void cpa16(uint32_t saddr, const void* g) {
    asm volatile("cp.async.cg.shared.global [%0], [%1], 16;"
                 :: "r"(saddr), "l"(g));
}
#define CPA_COMMIT() asm volatile("cp.async.commit_group;" ::: "memory")
#define CPA_WAIT1()  asm volatile("cp.async.wait_group 1;" ::: "memory")
#define CPA_WAIT0()  asm volatile("cp.async.wait_group 0;" ::: "memory")

// row-major tile: 128 rows x 64 halves
__device__ __forceinline__ void cpa_tile(uint32_t sbase_bytes,
                                         const __half* __restrict__ src,
                                         int ld, int row0, int k0, int t) {
    #pragma unroll
    for (int j = 0; j < 4; j++) {
        const int idx = t + 256 * j;
        const int r = idx >> 3, c8 = idx & 7;
        const void* g = src + (size_t)(row0 + r) * ld + k0 + c8 * 8;
        cpa16(sbase_bytes + (uint32_t)(r * PITCHW + c8 * 4) * 4u, g);
    }
}

// trans tile: 64 k-rows x 128 n-halves, native [k][n] layout
__device__ __forceinline__ void cpa_tile_bt(uint32_t sbase_bytes,
                                            const __half* __restrict__ src,
                                            int ld, int n0, int k0, int t) {
    #pragma unroll
    for (int j = 0; j < 4; j++) {
        const int idx = t + 256 * j;
        const int r = idx >> 4, c16 = idx & 15;
        const void* g = src + (size_t)(k0 + r) * ld + n0 + c16 * 8;
        cpa16(sbase_bytes + (uint32_t)(r * PITCHBT + c16 * 4) * 4u, g);
    }
}

__device__ __forceinline__ void mma16816(float d[4], const uint32_t a[4],
                                         const uint32_t b[2]) {
    asm volatile(
        "mma.sync.aligned.m16n8k16.row.col.f32.f16.f16.f32 "
        "{%0,%1,%2,%3}, {%4,%5,%6,%7}, {%8,%9}, {%0,%1,%2,%3};"
        : "+f"(d[0]), "+f"(d[1]), "+f"(d[2]), "+f"(d[3])
        : "r"(a[0]), "r"(a[1]), "r"(a[2]), "r"(a[3]), "r"(b[0]), "r"(b[1]));
}
#define LDMX4(r0, r1, r2, r3, addr) \
    asm volatile("ldmatrix.sync.aligned.m8n8.x4.shared.b16 {%0,%1,%2,%3}, [%4];" \
                 : "=r"(r0), "=r"(r1), "=r"(r2), "=r"(r3) : "r"(addr))
#define LDMX4T(r0, r1, r2, r3, addr) \
    asm volatile("ldmatrix.sync.aligned.m8n8.x4.trans.shared.b16 {%0,%1,%2,%3}, [%4];" \
                 : "=r"(r0), "=r"(r1), "=r"(r2), "=r"(r3) : "r"(addr))

// Load one ks-step's fragments (A: 4x ldmatrix.x4; B: 2x ldmatrix(.trans).x4)
template<int BT>
__device__ __forceinline__ void load_frags(uint32_t aBuf, uint32_t bBuf,
                                           uint32_t laneA, uint32_t laneB,
                                           int ks, uint32_t af[4][4],
                                           uint32_t bf[4][2]) {
    #pragma unroll
    for (int mf = 0; mf < 4; mf++)
        LDMX4(af[mf][0], af[mf][1], af[mf][2], af[mf][3],
              aBuf + laneA + (uint32_t)(mf * 16 * PITCHW * 4 + ks * 32));
    if (BT == 0) {
        LDMX4(bf[0][0], bf[0][1], bf[1][0], bf[1][1],
              bBuf + laneB + (uint32_t)(ks * 32));
        LDMX4(bf[2][0], bf[2][1], bf[3][0], bf[3][1],
              bBuf + laneB + (uint32_t)(16 * PITCHW * 4 + ks * 32));
    } else {
        LDMX4T(bf[0][0], bf[0][1], bf[1][0], bf[1][1],
               bBuf + laneB + (uint32_t)(ks * 16 * PITCHBT * 4));
        LDMX4T(bf[2][0], bf[2][1], bf[3][0], bf[3][1],
               bBuf + laneB + (uint32_t)(ks * 16 * PITCHBT * 4 + 32));
    }
}

// ---------------------------------------------------------------------------
// GEMM: C[m][n] = scale * sum_k A[m][k]*B'[n][k] (+bias) (+resid)
// A row-major (cp.async). BT=0: B row-major [n][k] (cp.async + ldmatrix);
// BT=1: B native [k][n] (cp.async + ldmatrix.trans). BIASMODE 0/1(row)/2(col).
// 128x128x64 tile, 8 warps, 2-stage double buffer, reg-double-buffered frags.
// ---------------------------------------------------------------------------
template<int BT, int BIASMODE, bool RESID, bool HOUT>
__global__ void __launch_bounds__(256, 2) hgemm(
    const __half* __restrict__ A, const __half* __restrict__ B,
    const float* __restrict__ bias, const float* __restrict__ resid,
    void* __restrict__ Cv, int N, int K, int ldA, int ldB,
    size_t sA, size_t sB, size_t sC, size_t sR, float scale)
{
    extern __shared__ __align__(16) uint32_t smbuf[];

    const int z = blockIdx.z;
    A += (size_t)z * sA;
    B += (size_t)z * sB;
    const float* R = RESID ? (resid + (size_t)z * sR) : nullptr;

    const int n0 = blockIdx.x * 128, m0 = blockIdx.y * 128;
    const int t = threadIdx.x;
    const int wid = t >> 5, lane = t & 31;
    const int wm = wid & 1, wn = wid >> 1;
    const int grp = lane >> 2, tig = lane & 3;

    const uint32_t smBase = (uint32_t)__cvta_generic_to_shared(smbuf);
    // slots (byte offsets): A0=0, B0=OPW*4, A1=2*OPW*4, B1=3*OPW*4

    float acc[4][4][4] = {};

    // prologue: chunk 0
    cpa_tile(smBase, A, ldA, m0, 0, t);
    if (BT == 0) cpa_tile(smBase + OPW * 4, B, ldB, n0, 0, t);
    else         cpa_tile_bt(smBase + OPW * 4, B, ldB, n0, 0, t);
    CPA_COMMIT();

    const uint32_t laneA =
        ((uint32_t)(wm * 64 + (lane & 7) + 8 * ((lane >> 3) & 1)) * PITCHW
         + 4u * ((lane >> 4) & 1)) * 4u;
    const uint32_t laneB = (BT == 0)
        ? ((uint32_t)(wn * 32 + (lane & 7) + 8 * ((lane >> 4) & 1)) * PITCHW
           + 4u * ((lane >> 3) & 1)) * 4u
        : (uint32_t)((lane & 7) + 8 * ((lane >> 3) & 1)) * (PITCHBT * 4)
          + (uint32_t)(wn * 32 + 8 * ((lane >> 4) & 1)) * 2u;

    const int NK = K >> 6;
    for (int kc = 0; kc < NK; kc++) {
        const bool more = (kc + 1 < NK);
        const uint32_t cur = (kc & 1) ? (uint32_t)(2 * OPW * 4) : 0u;
        const uint32_t nxt = (kc & 1) ? 0u : (uint32_t)(2 * OPW * 4);
        if (more) {
            cpa_tile(smBase + nxt, A, ldA, m0, (kc + 1) * 64, t);
            if (BT == 0) cpa_tile(smBase + nxt + OPW * 4, B, ldB, n0, (kc + 1) * 64, t);
            else         cpa_tile_bt(smBase + nxt + OPW * 4, B, ldB, n0, (kc + 1) * 64, t);
            CPA_COMMIT();
        }
        if (more) CPA_WAIT1(); else CPA_WAIT0();
        __syncthreads();

        const uint32_t aBuf = smBase + cur;
        const uint32_t bBuf = aBuf + (uint32_t)(OPW * 4);

        // register double-buffered fragments across ks
        uint32_t af[2][4][4], bf[2][4][2];
        load_frags<BT>(aBuf, bBuf, laneA, laneB, 0, af[0], bf[0]);
        #pragma unroll
        for (int ks = 0; ks < 4; ks++) {
            const int cb = ks & 1;
            if (ks < 3)
                load_frags<BT>(aBuf, bBuf, laneA, laneB, ks + 1, af[cb ^ 1], bf[cb ^ 1]);
            #pragma unroll
            for (int mf = 0; mf < 4; mf++)
                #pragma unroll
                for (int nf = 0; nf < 4; nf++)
                    mma16816(acc[mf][nf], af[cb][mf], bf[cb][nf]);
        }
        __syncthreads();
    }

    // ---- epilogue ----
    #pragma unroll
    for (int mf = 0; mf < 4; mf++) {
        const int r0 = m0 + wm * 64 + mf * 16 + grp;
        const float ba0 = (BIASMODE == 1) ? bias[r0] : 0.f;
        const float ba1 = (BIASMODE == 1) ? bias[r0 + 8] : 0.f;
        #pragma unroll
        for (int nf = 0; nf < 4; nf++) {
            const int cc = n0 + wn * 32 + nf * 8 + 2 * tig;
            float cb0 = 0.f, cb1 = 0.f;
            if (BIASMODE == 2) {
                const float2 cb = *reinterpret_cast<const float2*>(&bias[cc]);
                cb0 = cb.x; cb1 = cb.y;
            }
            float2 v0, v1;
            v0.x = acc[mf][nf][0] * scale + ba0 + cb0;
            v0.y = acc[mf][nf][1] * scale + ba0 + cb1;
            v1.x = acc[mf][nf][2] * scale + ba1 + cb0;
            v1.y = acc[mf][nf][3] * scale + ba1 + cb1;
            if (RESID) {
                const float2 q0 = *reinterpret_cast<const float2*>(&R[(size_t)r0 * N + cc]);
                const float2 q1 = *reinterpret_cast<const float2*>(&R[(size_t)(r0 + 8) * N + cc]);
                v0.x += q0.x; v0.y += q0.y;
                v1.x += q1.x; v1.y += q1.y;
            }
            if (HOUT) {
                __half* C = (__half*)Cv + (size_t)z * sC;
                *reinterpret_cast<__half2*>(&C[(size_t)r0 * N + cc]) =
                    __floats2half2_rn(v0.x, v0.y);
                *reinterpret_cast<__half2*>(&C[(size_t)(r0 + 8) * N + cc]) =
                    __floats2half2_rn(v1.x, v1.y);
            } else {
                float* C = (float*)Cv + (size_t)z * sC;
                *reinterpret_cast<float2*>(&C[(size_t)r0 * N + cc]) = v0;
                *reinterpret_cast<float2*>(&C[(size_t)(r0 + 8) * N + cc]) = v1;
            }
        }
    }
}

// ---------------------------------------------------------------------------
__global__ void __launch_bounds__(256) cvt_w_kernel(
    const float* __restrict__ w0, const float* __restrict__ w1,
    const float* __restrict__ w2, const float* __restrict__ w3,
    __half* __restrict__ wcat, __half* __restrict__ wp)
{
    const int zz = blockIdx.y;
    const float* src = (zz == 0) ? w0 : (zz == 1) ? w1 : (zz == 2) ? w2 : w3;
    __half* dst = (zz == 3) ? wp : (wcat + (size_t)zz * CCH * CCH);
    const int i = blockIdx.x * 256 + threadIdx.x;
    const float4 v = reinterpret_cast<const float4*>(src)[i];
    __half2* d = reinterpret_cast<__half2*>(dst) + i * 2;
    d[0] = __floats2half2_rn(v.x, v.y);
    d[1] = __floats2half2_rn(v.z, v.w);
}

__global__ void __launch_bounds__(256) bcat_kernel(
    const float* __restrict__ b0, const float* __restrict__ b1,
    const float* __restrict__ b2, float* __restrict__ bcat)
{
    const int i = blockIdx.x * 256 + threadIdx.x;
    bcat[i] = (i < 512) ? b0[i] : (i < 1024) ? b1[i - 512] : b2[i - 1024];
}

// ---------------------------------------------------------------------------
// GroupNorm -> token-major fp16
// ---------------------------------------------------------------------------
__global__ void __launch_bounds__(256) groupnorm_t_kernel(
    const float* __restrict__ x, const float* __restrict__ gamma,
    const float* __restrict__ beta, __half* __restrict__ hnT)
{
    const int g = blockIdx.x, b = blockIdx.y;
    const int c0 = g * CPG;
    const size_t xbase = ((size_t)b * CCH + c0) * NTOK;
    const int tid = threadIdx.x;

    const float4* xp = reinterpret_cast<const float4*>(x + xbase);
    float s = 0.f, ss = 0.f;
    for (int i = tid; i < GSIZE / 4; i += 256) {
        const float4 v = xp[i];
        s  += v.x + v.y + v.z + v.w;
        ss += v.x * v.x + v.y * v.y + v.z * v.z + v.w * v.w;
    }
    __shared__ float rs[256], rss[256];
    rs[tid] = s; rss[tid] = ss;
    __syncthreads();
    for (int w = 128; w > 0; w >>= 1) {
        if (tid < w) { rs[tid] += rs[tid + w]; rss[tid] += rss[tid + w]; }
        __syncthreads();
    }
    const float mean = rs[0] * (1.f / GSIZE);
    const float var  = rss[0] * (1.f / GSIZE) - mean * mean;
    const float rstd = rsqrtf(var + 1e-6f);

    __shared__ float gsc[CPG], gof[CPG];
    if (tid < CPG) {
        const float ga = gamma[c0 + tid] * rstd;
        gsc[tid] = ga;
        gof[tid] = beta[c0 + tid] - mean * ga;
    }
    __syncthreads();

    __shared__ __half smh[32 * 264];
    for (int tt = 0; tt < 4; tt++) {
        const int tok0 = tt * 256;
        #pragma unroll 4
        for (int j = 0; j < 32; j++) {
            const float val = x[xbase + (size_t)j * NTOK + tok0 + tid];
            smh[j * 264 + tid] = __float2half(val * gsc[j] + gof[j]);
        }
        __syncthreads();
        const size_t obase = ((size_t)b * NTOK + tok0 + tid) * CCH + c0;
        __half2 wb[16];
        #pragma unroll
        for (int j2 = 0; j2 < 16; j2++) {
            const __half lo = smh[(2 * j2) * 264 + tid];
            const __half hi = smh[(2 * j2 + 1) * 264 + tid];
            wb[j2] = __halves2half2(lo, hi);
        }
        #pragma unroll
        for (int qd = 0; qd < 4; qd++) {
            *reinterpret_cast<uint4*>(&hnT[obase + qd * 8]) =
                *reinterpret_cast<const uint4*>(&wb[qd * 4]);
        }
        __syncthreads();
    }
}

// ---------------------------------------------------------------------------
// Warp-per-row softmax: fp32 scores -> fp16 probs, pure shuffle reductions.
// (per-row max == reference's global shift, by softmax shift invariance)
// ---------------------------------------------------------------------------
__global__ void __launch_bounds__(256) softmax_kernel(
    const float* __restrict__ s, __half* __restrict__ attn)
{
    const int wid = threadIdx.x >> 5, lane = threadIdx.x & 31;
    const size_t row = (size_t)blockIdx.y * NTOK + blockIdx.x * 8 + wid;
    const float4* p = reinterpret_cast<const float4*>(s + row * NTOK);
    __half2*      o = reinterpret_cast<__half2*>(attn + row * NTOK);

    float4 v[8];
    float m = -3.4e38f;
    #pragma unroll
    for (int i = 0; i < 8; i++) {
        v[i] = p[lane + 32 * i];
        m = fmaxf(m, fmaxf(fmaxf(v[i].x, v[i].y), fmaxf(v[i].z, v[i].w)));
    }
    #pragma unroll
    for (int off = 16; off > 0; off >>= 1)
        m = fmaxf(m, __shfl_xor_sync(0xFFFFFFFFu, m, off));

    float sum = 0.f;
    #pragma unroll
    for (int i = 0; i < 8; i++) {
        v[i].x = __expf(v[i].x - m); v[i].y = __expf(v[i].y - m);
        v[i].z = __expf(v[i].z - m); v[i].w = __expf(v[i].w - m);
        sum += v[i].x + v[i].y + v[i].z + v[i].w;
    }
    #pragma unroll
    for (int off = 16; off > 0; off >>= 1)
        sum += __shfl_xor_sync(0xFFFFFFFFu, sum, off);
    const float inv = 1.f / sum;

    #pragma unroll
    for (int i = 0; i < 8; i++) {
        o[(lane + 32 * i) * 2 + 0] = __floats2half2_rn(v[i].x * inv, v[i].y * inv);
        o[(lane + 32 * i) * 2 + 1] = __floats2half2_rn(v[i].z * inv, v[i].w * inv);
    }
}

// ---------------------------------------------------------------------------
extern "C" void kernel_launch(void* const* d_in, const int* in_sizes, int n_in,
                              void* d_out, int out_size)
{
    (void)in_sizes; (void)n_in; (void)out_size;
    const float* x     = (const float*)d_in[0];
    const float* gamma = (const float*)d_in[1];
    const float* beta  = (const float*)d_in[2];
    const float* wq    = (const float*)d_in[3];
    const float* bq    = (const float*)d_in[4];
    const float* wk    = (const float*)d_in[5];
    const float* bk    = (const float*)d_in[6];
    const float* wv    = (const float*)d_in[7];
    const float* bv    = (const float*)d_in[8];
    const float* wp    = (const float*)d_in[9];
    const float* bp    = (const float*)d_in[10];
    float* out = (float*)d_out;

    void *p0, *p1, *p2, *p3, *p4, *p5, *p6, *p7;
    cudaGetSymbolAddress(&p0, sc_hnT);
    cudaGetSymbolAddress(&p1, sc_qkv);
    cudaGetSymbolAddress(&p2, sc_s);
    cudaGetSymbolAddress(&p3, sc_at);
    cudaGetSymbolAddress(&p4, sc_oT);
    cudaGetSymbolAddress(&p5, sc_wcat);
    cudaGetSymbolAddress(&p6, sc_wp);
    cudaGetSymbolAddress(&p7, sc_bcat);
    __half* hnT  = (__half*)p0;
    __half* qkv  = (__half*)p1;
    float*  s    = (float*)p2;
    __half* at   = (__half*)p3;
    __half* oT   = (__half*)p4;
    __half* wcat = (__half*)p5;
    __half* whp  = (__half*)p6;
    float*  bcat = (float*)p7;

    const size_t sHN  = (size_t)NTOK * CCH;
    const size_t sQKV = (size_t)NTOK * 3 * CCH;
    const size_t sS   = (size_t)NTOK * NTOK;

    cudaFuncSetAttribute(hgemm<0, 2, false, true>,
        cudaFuncAttributeMaxDynamicSharedMemorySize, GEMM_SMEM_BYTES);
    cudaFuncSetAttribute(hgemm<0, 0, false, false>,
        cudaFuncAttributeMaxDynamicSharedMemorySize, GEMM_SMEM_BYTES);
    cudaFuncSetAttribute(hgemm<1, 0, false, true>,
        cudaFuncAttributeMaxDynamicSharedMemorySize, GEMM_SMEM_BYTES);
    cudaFuncSetAttribute(hgemm<0, 1, true, false>,
        cudaFuncAttributeMaxDynamicSharedMemorySize, GEMM_SMEM_BYTES);

    cvt_w_kernel<<<dim3(256, 4), 256>>>(wq, wk, wv, wp, wcat, whp);
    bcat_kernel<<<6, 256>>>(bq, bk, bv, bcat);
    groupnorm_t_kernel<<<dim3(NGRP, BATCH), 256>>>(x, gamma, beta, hnT);

    // 1) fused QKV: qkv[token][oc'] = hnT[token][c] . wcat[oc'][c] + bcat[oc']
    hgemm<0, 2, false, true><<<dim3(12, 8, BATCH), 256, GEMM_SMEM_BYTES>>>(
        hnT, wcat, bcat, nullptr, qkv, 3 * CCH, CCH, CCH, CCH,
        sHN, 0, sQKV, 0, 1.f);

    // 2) scores s[n][m] = scale * q[n][:] . k[m][:]
    hgemm<0, 0, false, false><<<dim3(8, 8, BATCH), 256, GEMM_SMEM_BYTES>>>(
        qkv, qkv + CCH, nullptr, nullptr, s, NTOK, CCH, 3 * CCH, 3 * CCH,
        sQKV, sQKV, sS, 0, 0.04419417382415922f);

    // 3) softmax
    softmax_kernel<<<dim3(NTOK / 8, BATCH), 256>>>(s, at);

    // 4) oT[n][c] = sum_m at[n][m] * v[m][c]
    //    (B = v native [k][n] layout -> cp.async + ldmatrix.trans)
    hgemm<1, 0, false, true><<<dim3(4, 8, BATCH), 256, GEMM_SMEM_BYTES>>>(
        at, qkv + 2 * CCH, nullptr, nullptr, oT, CCH, NTOK, NTOK, 3 * CCH,
        sS, sQKV, sHN, 0, 1.f);

    // 5) out[oc][n] = x + wp[oc][:] . oT[n][:] + bp[oc]
    hgemm<0, 1, true, false><<<dim3(8, 4, BATCH), 256, GEMM_SMEM_BYTES>>>(
        whp, oT, bp, x, out, NTOK, CCH, CCH, CCH,
        0, sHN, sHN, sHN, 1.f);
}

// round 14
// speedup vs baseline: 1.5507x; 1.0256x over previous
#include <cuda_runtime.h>
#include <cuda_fp16.h>
#include <cstdint>
#include <cstddef>

// ===========================================================================
// AttnBlock, fp16 mma.sync, token-major intermediates, cp.async pipeline,
// trans-B via cp.async + ldmatrix.trans, fp16 scores + in-place softmax.
// b=32, c=512, n=1024, groups=16
// ===========================================================================

#define BATCH 32
#define CCH   512
#define NTOK  1024
#define NGRP  16
#define CPG   (CCH / NGRP)
#define GSIZE (CPG * NTOK)

__device__ __half sc_hnT [(size_t)BATCH * NTOK * CCH];
__device__ __half sc_qkv [(size_t)BATCH * NTOK * 3 * CCH];
__device__ __half sc_at  [(size_t)BATCH * NTOK * NTOK];   // scores -> attn (in place)
__device__ __half sc_oT  [(size_t)BATCH * NTOK * CCH];
__device__ __half sc_wcat[(size_t)3 * CCH * CCH];
__device__ __half sc_wp  [(size_t)CCH * CCH];
__device__ float  sc_bcat[3 * CCH];

// Row-major operand: [row 0..127][kw 0..31], pitch 36 words (18432 B).
// Trans-B operand:   [k 0..63][n-half 0..63], pitch 68 words (17408 B).
// Both: 8 consecutive rows start at {0,4,...,28} mod 32 -> ldmatrix
// 16B-granule reads tile all 32 banks, conflict-free.
#define PITCHW  36
#define PITCHBT 68
#define OPW     (128 * PITCHW)             // words per operand slot (4608)
#define GEMM_SMEM_BYTES (4 * OPW * 4)      // A0 B0 A1 B1 = 73728 B

__device__ __forceinline__ void cpa16(uint32_t saddr, const void* g) {
    asm volatile("cp.async.cg.shared.global [%0], [%1], 16;"
                 :: "r"(saddr), "l"(g));
}
#define CPA_COMMIT() asm volatile("cp.async.commit_group;" ::: "memory")
#define CPA_WAIT1()  asm volatile("cp.async.wait_group 1;" ::: "memory")
#define CPA_WAIT0()  asm volatile("cp.async.wait_group 0;" ::: "memory")

// row-major tile: 128 rows x 64 halves
__device__ __forceinline__ void cpa_tile(uint32_t sbase_bytes,
                                         const __half* __restrict__ src,
                                         int ld, int row0, int k0, int t) {
    #pragma unroll
    for (int j = 0; j < 4; j++) {
        const int idx = t + 256 * j;
        const int r = idx >> 3, c8 = idx & 7;
        const void* g = src + (size_t)(row0 + r) * ld + k0 + c8 * 8;
        cpa16(sbase_bytes + (uint32_t)(r * PITCHW + c8 * 4) * 4u, g);
    }
}

// trans tile: 64 k-rows x 128 n-halves, native [k][n] layout
__device__ __forceinline__ void cpa_tile_bt(uint32_t sbase_bytes,
                                            const __half* __restrict__ src,
                                            int ld, int n0, int k0, int t) {
    #pragma unroll
    for (int j = 0; j < 4; j++) {
        const int idx = t + 256 * j;
        const int r = idx >> 4, c16 = idx & 15;
        const void* g = src + (size_t)(k0 + r) * ld + n0 + c16 * 8;
        cpa16(sbase_bytes + (uint32_t)(r * PITCHBT + c16 * 4) * 4u, g);
    }
}

__device__ __forceinline__ void mma16816(float d[4], const uint32_t a[4],
                                         const uint32_t b[2]) {
    asm volatile(
        "mma.sync.aligned.m16n8k16.row.col.f32.f16.f16.f32 "
        "{%0,%1,%2,%3}, {%4,%5,%6,%7}, {%8,%9}, {%0,%1,%2,%3};"
        : "+f"(d[0]), "+f"(d[1]), "+f"(d[2]), "+f"(d[3])
        : "r"(a[0]), "r"(a[1]), "r"(a[2]), "r"(a[3]), "r"(b[0]), "r"(b[1]));
}
#define LDMX4(r0, r1, r2, r3, addr) \
    asm volatile("ldmatrix.sync.aligned.m8n8.x4.shared.b16 {%0,%1,%2,%3}, [%4];" \
                 : "=r"(r0), "=r"(r1), "=r"(r2), "=r"(r3) : "r"(addr))
#define LDMX4T(r0, r1, r2, r3, addr) \
    asm volatile("ldmatrix.sync.aligned.m8n8.x4.trans.shared.b16 {%0,%1,%2,%3}, [%4];" \
                 : "=r"(r0), "=r"(r1), "=r"(r2), "=r"(r3) : "r"(addr))

// Load one ks-step's fragments (A: 4x ldmatrix.x4; B: 2x ldmatrix(.trans).x4)
template<int BT>
__device__ __forceinline__ void load_frags(uint32_t aBuf, uint32_t bBuf,
                                           uint32_t laneA, uint32_t laneB,
                                           int ks, uint32_t af[4][4],
                                           uint32_t bf[4][2]) {
    #pragma unroll
    for (int mf = 0; mf < 4; mf++)
        LDMX4(af[mf][0], af[mf][1], af[mf][2], af[mf][3],
              aBuf + laneA + (uint32_t)(mf * 16 * PITCHW * 4 + ks * 32));
    if (BT == 0) {
        LDMX4(bf[0][0], bf[0][1], bf[1][0], bf[1][1],
              bBuf + laneB + (uint32_t)(ks * 32));
        LDMX4(bf[2][0], bf[2][1], bf[3][0], bf[3][1],
              bBuf + laneB + (uint32_t)(16 * PITCHW * 4 + ks * 32));
    } else {
        LDMX4T(bf[0][0], bf[0][1], bf[1][0], bf[1][1],
               bBuf + laneB + (uint32_t)(ks * 16 * PITCHBT * 4));
        LDMX4T(bf[2][0], bf[2][1], bf[3][0], bf[3][1],
               bBuf + laneB + (uint32_t)(ks * 16 * PITCHBT * 4 + 32));
    }
}

// ---------------------------------------------------------------------------
// GEMM: C[m][n] = scale * sum_k A[m][k]*B'[n][k] (+bias) (+resid)
// A row-major (cp.async). BT=0: B row-major [n][k]; BT=1: B native [k][n]
// (cp.async + ldmatrix.trans). BIASMODE 0/1(row)/2(col). HOUT fp16/fp32.
// 128x128x64 tile, 8 warps, 2-stage double buffer, reg-double-buffered frags.
// ---------------------------------------------------------------------------
template<int BT, int BIASMODE, bool RESID, bool HOUT>
__global__ void __launch_bounds__(256, 2) hgemm(
    const __half* __restrict__ A, const __half* __restrict__ B,
    const float* __restrict__ bias, const float* __restrict__ resid,
    void* __restrict__ Cv, int N, int K, int ldA, int ldB,
    size_t sA, size_t sB, size_t sC, size_t sR, float scale)
{
    extern __shared__ __align__(16) uint32_t smbuf[];

    const int z = blockIdx.z;
    A += (size_t)z * sA;
    B += (size_t)z * sB;
    const float* R = RESID ? (resid + (size_t)z * sR) : nullptr;

    const int n0 = blockIdx.x * 128, m0 = blockIdx.y * 128;
    const int t = threadIdx.x;
    const int wid = t >> 5, lane = t & 31;
    const int wm = wid & 1, wn = wid >> 1;
    const int grp = lane >> 2, tig = lane & 3;

    const uint32_t smBase = (uint32_t)__cvta_generic_to_shared(smbuf);

    float acc[4][4][4] = {};

    // prologue: chunk 0
    cpa_tile(smBase, A, ldA, m0, 0, t);
    if (BT == 0) cpa_tile(smBase + OPW * 4, B, ldB, n0, 0, t);
    else         cpa_tile_bt(smBase + OPW * 4, B, ldB, n0, 0, t);
    CPA_COMMIT();

    const uint32_t laneA =
        ((uint32_t)(wm * 64 + (lane & 7) + 8 * ((lane >> 3) & 1)) * PITCHW
         + 4u * ((lane >> 4) & 1)) * 4u;
    const uint32_t laneB = (BT == 0)
        ? ((uint32_t)(wn * 32 + (lane & 7) + 8 * ((lane >> 4) & 1)) * PITCHW
           + 4u * ((lane >> 3) & 1)) * 4u
        : (uint32_t)((lane & 7) + 8 * ((lane >> 3) & 1)) * (PITCHBT * 4)
          + (uint32_t)(wn * 32 + 8 * ((lane >> 4) & 1)) * 2u;

    const int NK = K >> 6;
    for (int kc = 0; kc < NK; kc++) {
        const bool more = (kc + 1 < NK);
        const uint32_t cur = (kc & 1) ? (uint32_t)(2 * OPW * 4) : 0u;
        const uint32_t nxt = (kc & 1) ? 0u : (uint32_t)(2 * OPW * 4);
        if (more) {
            cpa_tile(smBase + nxt, A, ldA, m0, (kc + 1) * 64, t);
            if (BT == 0) cpa_tile(smBase + nxt + OPW * 4, B, ldB, n0, (kc + 1) * 64, t);
            else         cpa_tile_bt(smBase + nxt + OPW * 4, B, ldB, n0, (kc + 1) * 64, t);
            CPA_COMMIT();
        }
        if (more) CPA_WAIT1(); else CPA_WAIT0();
        __syncthreads();

        const uint32_t aBuf = smBase + cur;
        const uint32_t bBuf = aBuf + (uint32_t)(OPW * 4);

        uint32_t af[2][4][4], bf[2][4][2];
        load_frags<BT>(aBuf, bBuf, laneA, laneB, 0, af[0], bf[0]);
        #pragma unroll
        for (int ks = 0; ks < 4; ks++) {
            const int cb = ks & 1;
            if (ks < 3)
                load_frags<BT>(aBuf, bBuf, laneA, laneB, ks + 1, af[cb ^ 1], bf[cb ^ 1]);
            #pragma unroll
            for (int mf = 0; mf < 4; mf++)
                #pragma unroll
                for (int nf = 0; nf < 4; nf++)
                    mma16816(acc[mf][nf], af[cb][mf], bf[cb][nf]);
        }
        __syncthreads();
    }

    // ---- epilogue ----
    #pragma unroll
    for (int mf = 0; mf < 4; mf++) {
        const int r0 = m0 + wm * 64 + mf * 16 + grp;
        const float ba0 = (BIASMODE == 1) ? bias[r0] : 0.f;
        const float ba1 = (BIASMODE == 1) ? bias[r0 + 8] : 0.f;
        #pragma unroll
        for (int nf = 0; nf < 4; nf++) {
            const int cc = n0 + wn * 32 + nf * 8 + 2 * tig;
            float cb0 = 0.f, cb1 = 0.f;
            if (BIASMODE == 2) {
                const float2 cb = *reinterpret_cast<const float2*>(&bias[cc]);
                cb0 = cb.x; cb1 = cb.y;
            }
            float2 v0, v1;
            v0.x = acc[mf][nf][0] * scale + ba0 + cb0;
            v0.y = acc[mf][nf][1] * scale + ba0 + cb1;
            v1.x = acc[mf][nf][2] * scale + ba1 + cb0;
            v1.y = acc[mf][nf][3] * scale + ba1 + cb1;
            if (RESID) {
                const float2 q0 = *reinterpret_cast<const float2*>(&R[(size_t)r0 * N + cc]);
                const float2 q1 = *reinterpret_cast<const float2*>(&R[(size_t)(r0 + 8) * N + cc]);
                v0.x += q0.x; v0.y += q0.y;
                v1.x += q1.x; v1.y += q1.y;
            }
            if (HOUT) {
                __half* C = (__half*)Cv + (size_t)z * sC;
                *reinterpret_cast<__half2*>(&C[(size_t)r0 * N + cc]) =
                    __floats2half2_rn(v0.x, v0.y);
                *reinterpret_cast<__half2*>(&C[(size_t)(r0 + 8) * N + cc]) =
                    __floats2half2_rn(v1.x, v1.y);
            } else {
                float* C = (float*)Cv + (size_t)z * sC;
                *reinterpret_cast<float2*>(&C[(size_t)r0 * N + cc]) = v0;
                *reinterpret_cast<float2*>(&C[(size_t)(r0 + 8) * N + cc]) = v1;
            }
        }
    }
}

// ---------------------------------------------------------------------------
// Weight + bias conversion, one launch: zz 0..2 -> wcat, 3 -> wp, 4 -> bcat
// ---------------------------------------------------------------------------
__global__ void __launch_bounds__(256) cvt_wb_kernel(
    const float* __restrict__ w0, const float* __restrict__ w1,
    const float* __restrict__ w2, const float* __restrict__ w3,
    const float* __restrict__ b0, const float* __restrict__ b1,
    const float* __restrict__ b2,
    __half* __restrict__ wcat, __half* __restrict__ wp,
    float* __restrict__ bcat)
{
    const int zz = blockIdx.y;
    const int i = blockIdx.x * 256 + threadIdx.x;
    if (zz == 4) {
        if (i < 3 * CCH)
            bcat[i] = (i < 512) ? b0[i] : (i < 1024) ? b1[i - 512] : b2[i - 1024];
        return;
    }
    const float* src = (zz == 0) ? w0 : (zz == 1) ? w1 : (zz == 2) ? w2 : w3;
    __half* dst = (zz == 3) ? wp : (wcat + (size_t)zz * CCH * CCH);
    const float4 v = reinterpret_cast<const float4*>(src)[i];
    __half2* d = reinterpret_cast<__half2*>(dst) + i * 2;
    d[0] = __floats2half2_rn(v.x, v.y);
    d[1] = __floats2half2_rn(v.z, v.w);
}

// ---------------------------------------------------------------------------
// GroupNorm -> token-major fp16
// ---------------------------------------------------------------------------
__global__ void __launch_bounds__(256) groupnorm_t_kernel(
    const float* __restrict__ x, const float* __restrict__ gamma,
    const float* __restrict__ beta, __half* __restrict__ hnT)
{
    const int g = blockIdx.x, b = blockIdx.y;
    const int c0 = g * CPG;
    const size_t xbase = ((size_t)b * CCH + c0) * NTOK;
    const int tid = threadIdx.x;

    const float4* xp = reinterpret_cast<const float4*>(x + xbase);
    float s = 0.f, ss = 0.f;
    for (int i = tid; i < GSIZE / 4; i += 256) {
        const float4 v = xp[i];
        s  += v.x + v.y + v.z + v.w;
        ss += v.x * v.x + v.y * v.y + v.z * v.z + v.w * v.w;
    }
    __shared__ float rs[256], rss[256];
    rs[tid] = s; rss[tid] = ss;
    __syncthreads();
    for (int w = 128; w > 0; w >>= 1) {
        if (tid < w) { rs[tid] += rs[tid + w]; rss[tid] += rss[tid + w]; }
        __syncthreads();
    }
    const float mean = rs[0] * (1.f / GSIZE);
    const float var  = rss[0] * (1.f / GSIZE) - mean * mean;
    const float rstd = rsqrtf(var + 1e-6f);

    __shared__ float gsc[CPG], gof[CPG];
    if (tid < CPG) {
        const float ga = gamma[c0 + tid] * rstd;
        gsc[tid] = ga;
        gof[tid] = beta[c0 + tid] - mean * ga;
    }
    __syncthreads();

    __shared__ __half smh[32 * 264];
    for (int tt = 0; tt < 4; tt++) {
        const int tok0 = tt * 256;
        #pragma unroll 4
        for (int j = 0; j < 32; j++) {
            const float val = x[xbase + (size_t)j * NTOK + tok0 + tid];
            smh[j * 264 + tid] = __float2half(val * gsc[j] + gof[j]);
        }
        __syncthreads();
        const size_t obase = ((size_t)b * NTOK + tok0 + tid) * CCH + c0;
        __half2 wb[16];
        #pragma unroll
        for (int j2 = 0; j2 < 16; j2++) {
            const __half lo = smh[(2 * j2) * 264 + tid];
            const __half hi = smh[(2 * j2 + 1) * 264 + tid];
            wb[j2] = __halves2half2(lo, hi);
        }
        #pragma unroll
        for (int qd = 0; qd < 4; qd++) {
            *reinterpret_cast<uint4*>(&hnT[obase + qd * 8]) =
                *reinterpret_cast<const uint4*>(&wb[qd * 4]);
        }
        __syncthreads();
    }
}

// ---------------------------------------------------------------------------
// Warp-per-row softmax, fp16 in/out, IN PLACE. Pure shuffle reductions.
// (per-row max == reference's global shift, by softmax shift invariance)
// ---------------------------------------------------------------------------
__global__ void __launch_bounds__(256) softmax_kernel(__half* __restrict__ at)
{
    const int wid = threadIdx.x >> 5, lane = threadIdx.x & 31;
    const size_t row = (size_t)blockIdx.y * NTOK + blockIdx.x * 8 + wid;
    uint4* p = reinterpret_cast<uint4*>(at + row * NTOK);

    // 4 x uint4 per lane = 32 halves
    uint4 raw[4];
    float v[4][8];
    float m = -3.4e38f;
    #pragma unroll
    for (int i = 0; i < 4; i++) {
        raw[i] = p[lane + 32 * i];
        const uint32_t* w = reinterpret_cast<const uint32_t*>(&raw[i]);
        #pragma unroll
        for (int j = 0; j < 4; j++) {
            const float2 f = __half22float2(*reinterpret_cast<const __half2*>(&w[j]));
            v[i][2 * j] = f.x; v[i][2 * j + 1] = f.y;
            m = fmaxf(m, fmaxf(f.x, f.y));
        }
    }
    #pragma unroll
    for (int off = 16; off > 0; off >>= 1)
        m = fmaxf(m, __shfl_xor_sync(0xFFFFFFFFu, m, off));

    float sum = 0.f;
    #pragma unroll
    for (int i = 0; i < 4; i++)
        #pragma unroll
        for (int j = 0; j < 8; j++) {
            v[i][j] = __expf(v[i][j] - m);
            sum += v[i][j];
        }
    #pragma unroll
    for (int off = 16; off > 0; off >>= 1)
        sum += __shfl_xor_sync(0xFFFFFFFFu, sum, off);
    const float inv = 1.f / sum;

    #pragma unroll
    for (int i = 0; i < 4; i++) {
        uint4 outw;
        uint32_t* w = reinterpret_cast<uint32_t*>(&outw);
        #pragma unroll
        for (int j = 0; j < 4; j++) {
            const __half2 h = __floats2half2_rn(v[i][2 * j] * inv, v[i][2 * j + 1] * inv);
            w[j] = *reinterpret_cast<const uint32_t*>(&h);
        }
        p[lane + 32 * i] = outw;
    }
}

// ---------------------------------------------------------------------------
extern "C" void kernel_launch(void* const* d_in, const int* in_sizes, int n_in,
                              void* d_out, int out_size)
{
    (void)in_sizes; (void)n_in; (void)out_size;
    const float* x     = (const float*)d_in[0];
    const float* gamma = (const float*)d_in[1];
    const float* beta  = (const float*)d_in[2];
    const float* wq    = (const float*)d_in[3];
    const float* bq    = (const float*)d_in[4];
    const float* wk    = (const float*)d_in[5];
    const float* bk    = (const float*)d_in[6];
    const float* wv    = (const float*)d_in[7];
    const float* bv    = (const float*)d_in[8];
    const float* wp    = (const float*)d_in[9];
    const float* bp    = (const float*)d_in[10];
    float* out = (float*)d_out;

    void *p0, *p1, *p3, *p4, *p5, *p6, *p7;
    cudaGetSymbolAddress(&p0, sc_hnT);
    cudaGetSymbolAddress(&p1, sc_qkv);
    cudaGetSymbolAddress(&p3, sc_at);
    cudaGetSymbolAddress(&p4, sc_oT);
    cudaGetSymbolAddress(&p5, sc_wcat);
    cudaGetSymbolAddress(&p6, sc_wp);
    cudaGetSymbolAddress(&p7, sc_bcat);
    __half* hnT  = (__half*)p0;
    __half* qkv  = (__half*)p1;
    __half* at   = (__half*)p3;
    __half* oT   = (__half*)p4;
    __half* wcat = (__half*)p5;
    __half* whp  = (__half*)p6;
    float*  bcat = (float*)p7;

    const size_t sHN  = (size_t)NTOK * CCH;
    const size_t sQKV = (size_t)NTOK * 3 * CCH;
    const size_t sS   = (size_t)NTOK * NTOK;

    cudaFuncSetAttribute(hgemm<0, 2, false, true>,
        cudaFuncAttributeMaxDynamicSharedMemorySize, GEMM_SMEM_BYTES);
    cudaFuncSetAttribute(hgemm<0, 0, false, true>,
        cudaFuncAttributeMaxDynamicSharedMemorySize, GEMM_SMEM_BYTES);
    cudaFuncSetAttribute(hgemm<1, 0, false, true>,
        cudaFuncAttributeMaxDynamicSharedMemorySize, GEMM_SMEM_BYTES);
    cudaFuncSetAttribute(hgemm<0, 1, true, false>,
        cudaFuncAttributeMaxDynamicSharedMemorySize, GEMM_SMEM_BYTES);

    cvt_wb_kernel<<<dim3(256, 5), 256>>>(wq, wk, wv, wp, bq, bk, bv,
                                         wcat, whp, bcat);
    groupnorm_t_kernel<<<dim3(NGRP, BATCH), 256>>>(x, gamma, beta, hnT);

    // 1) fused QKV: qkv[token][oc'] = hnT[token][c] . wcat[oc'][c] + bcat[oc']
    hgemm<0, 2, false, true><<<dim3(12, 8, BATCH), 256, GEMM_SMEM_BYTES>>>(
        hnT, wcat, bcat, nullptr, qkv, 3 * CCH, CCH, CCH, CCH,
        sHN, 0, sQKV, 0, 1.f);

    // 2) scores (fp16 out) s[n][m] = scale * q[n][:] . k[m][:]
    hgemm<0, 0, false, true><<<dim3(8, 8, BATCH), 256, GEMM_SMEM_BYTES>>>(
        qkv, qkv + CCH, nullptr, nullptr, at, NTOK, CCH, 3 * CCH, 3 * CCH,
        sQKV, sQKV, sS, 0, 0.04419417382415922f);

    // 3) softmax, in place on fp16 scores
    softmax_kernel<<<dim3(NTOK / 8, BATCH), 256>>>(at);

    // 4) oT[n][c] = sum_m at[n][m] * v[m][c]
    //    (B = v native [k][n] layout -> cp.async + ldmatrix.trans)
    hgemm<1, 0, false, true><<<dim3(4, 8, BATCH), 256, GEMM_SMEM_BYTES>>>(
        at, qkv + 2 * CCH, nullptr, nullptr, oT, CCH, NTOK, NTOK, 3 * CCH,
        sS, sQKV, sHN, 0, 1.f);

    // 5) out[oc][n] = x + wp[oc][:] . oT[n][:] + bp[oc]
    hgemm<0, 1, true, false><<<dim3(8, 4, BATCH), 256, GEMM_SMEM_BYTES>>>(
        whp, oT, bp, x, out, NTOK, CCH, CCH, CCH,
        0, sHN, sHN, sHN, 1.f);
}